// round 1
// baseline (speedup 1.0000x reference)
#include <cuda_runtime.h>
#include <cstdint>

// ---------------------------------------------------------------------------
// VLMSpatialHead:
//   X   = hidden[flat_idx]            [N_TOK, H]       (H = 2048)
//   Hm  = mish(X @ W1^T + b1)         [N_TOK, D_MID]   (D_MID = 1024)
//   S   = Hm @ W2^T + b2              [N_TOK, D_OUT]   (D_OUT = 256)
//   out = segment_sum(S, segment_ids) [N_IMG, D_OUT]
//
// Round 0: fp32 CUDA-core SGEMM baseline (128x128x16 tiles, 8x8/thread),
// fused epilogues, deterministic segment pooling (no atomics).
// ---------------------------------------------------------------------------

#define NTOK_MAX 32768
#define DMID     1024
#define DOUT     256

// Scratch (device globals: allocation-free per harness rules)
__device__ float g_H[(size_t)NTOK_MAX * DMID];   // 134 MB
__device__ float g_S[(size_t)NTOK_MAX * DOUT];   // 33.5 MB

__device__ __forceinline__ float mishf(float x) {
    // softplus(x) = max(x,0) + log1p(exp(-|x|))  (stable both directions)
    float sp = fmaxf(x, 0.0f) + log1pf(__expf(-fabsf(x)));
    return x * tanhf(sp);
}

// C[bm:bm+128, bn:bn+128] = act( A_rows @ W^T + bias )
// A: rows selected by rowmap (gather) or identity, K-contiguous [*, KD]
// W: [Nout, KD] row-major (K-contiguous) -> C[n,m] = sum_k A[n,k] * W[m,k]
template<int KD, bool GATHER, bool MISH>
__global__ void __launch_bounds__(256, 2)
gemm_bias_act(const float* __restrict__ A,
              const float* __restrict__ W,
              const float* __restrict__ bias,
              const int*   __restrict__ gidx,
              float*       __restrict__ out,
              int ldo)
{
    constexpr int BM = 128, BN = 128, BK = 16;
    __shared__ float As[BK][BM];
    __shared__ float Bs[BK][BN];
    __shared__ int   rowmap[BM];

    const int tid = threadIdx.x;
    const int bm  = blockIdx.x * BM;
    const int bn  = blockIdx.y * BN;

    if (tid < BM) rowmap[tid] = GATHER ? gidx[bm + tid] : (bm + tid);
    __syncthreads();

    // Global-load assignment: thread loads 2 float4 of A-tile and 2 of W-tile.
    const int r0 = tid >> 2;          // 0..63
    const int r1 = r0 + 64;           // 64..127
    const int kq = (tid & 3) << 2;    // 0,4,8,12

    const float* pa0 = A + (size_t)rowmap[r0] * KD + kq;
    const float* pa1 = A + (size_t)rowmap[r1] * KD + kq;
    const float* pw0 = W + (size_t)(bn + r0) * KD + kq;
    const float* pw1 = W + (size_t)(bn + r1) * KD + kq;

    // Compute assignment: 16x16 thread grid, 8x8 accumulator each.
    const int tx = (tid & 15) << 3;   // col offset in tile (N dim)
    const int ty = (tid >> 4) << 3;   // row offset in tile (M/token dim)

    float acc[8][8];
    #pragma unroll
    for (int i = 0; i < 8; i++)
        #pragma unroll
        for (int j = 0; j < 8; j++) acc[i][j] = 0.0f;

    for (int k0 = 0; k0 < KD; k0 += BK) {
        float4 a0 = *reinterpret_cast<const float4*>(pa0 + k0);
        float4 a1 = *reinterpret_cast<const float4*>(pa1 + k0);
        float4 w0 = *reinterpret_cast<const float4*>(pw0 + k0);
        float4 w1 = *reinterpret_cast<const float4*>(pw1 + k0);

        As[kq+0][r0] = a0.x; As[kq+1][r0] = a0.y; As[kq+2][r0] = a0.z; As[kq+3][r0] = a0.w;
        As[kq+0][r1] = a1.x; As[kq+1][r1] = a1.y; As[kq+2][r1] = a1.z; As[kq+3][r1] = a1.w;
        Bs[kq+0][r0] = w0.x; Bs[kq+1][r0] = w0.y; Bs[kq+2][r0] = w0.z; Bs[kq+3][r0] = w0.w;
        Bs[kq+0][r1] = w1.x; Bs[kq+1][r1] = w1.y; Bs[kq+2][r1] = w1.z; Bs[kq+3][r1] = w1.w;
        __syncthreads();

        #pragma unroll
        for (int kk = 0; kk < BK; kk++) {
            float4 ra0 = *reinterpret_cast<const float4*>(&As[kk][ty]);
            float4 ra1 = *reinterpret_cast<const float4*>(&As[kk][ty + 4]);
            float4 rb0 = *reinterpret_cast<const float4*>(&Bs[kk][tx]);
            float4 rb1 = *reinterpret_cast<const float4*>(&Bs[kk][tx + 4]);
            float ra[8] = {ra0.x, ra0.y, ra0.z, ra0.w, ra1.x, ra1.y, ra1.z, ra1.w};
            float rb[8] = {rb0.x, rb0.y, rb0.z, rb0.w, rb1.x, rb1.y, rb1.z, rb1.w};
            #pragma unroll
            for (int i = 0; i < 8; i++)
                #pragma unroll
                for (int j = 0; j < 8; j++)
                    acc[i][j] = fmaf(ra[i], rb[j], acc[i][j]);
        }
        __syncthreads();
    }

    // Epilogue: bias (+ mish) + store
    float4 bv0 = *reinterpret_cast<const float4*>(bias + bn + tx);
    float4 bv1 = *reinterpret_cast<const float4*>(bias + bn + tx + 4);
    float bcol[8] = {bv0.x, bv0.y, bv0.z, bv0.w, bv1.x, bv1.y, bv1.z, bv1.w};

    #pragma unroll
    for (int i = 0; i < 8; i++) {
        const int row = bm + ty + i;
        float v[8];
        #pragma unroll
        for (int j = 0; j < 8; j++) {
            float t = acc[i][j] + bcol[j];
            v[j] = MISH ? mishf(t) : t;
        }
        float4 o0 = make_float4(v[0], v[1], v[2], v[3]);
        float4 o1 = make_float4(v[4], v[5], v[6], v[7]);
        *reinterpret_cast<float4*>(&out[(size_t)row * ldo + bn + tx])     = o0;
        *reinterpret_cast<float4*>(&out[(size_t)row * ldo + bn + tx + 4]) = o1;
    }
}

// Deterministic segment-sum: one block per segment, one thread per out column.
// segment_ids is sorted, so each segment is a contiguous token range found by
// binary search. Fixed summation order -> bit-deterministic, no atomics.
__global__ void __launch_bounds__(256)
pool_kernel(const float* __restrict__ S, const int* __restrict__ seg,
            int n_tok, float* __restrict__ out)
{
    const int g   = blockIdx.x;
    const int col = threadIdx.x;

    // lower_bound(seg, g) and lower_bound(seg, g+1)
    int lo = 0, hi = n_tok;
    while (lo < hi) { int mid = (lo + hi) >> 1; if (seg[mid] < g) lo = mid + 1; else hi = mid; }
    const int s = lo;
    lo = s; hi = n_tok;
    while (lo < hi) { int mid = (lo + hi) >> 1; if (seg[mid] < g + 1) lo = mid + 1; else hi = mid; }
    const int e = lo;

    float a0 = 0.f, a1 = 0.f, a2 = 0.f, a3 = 0.f;
    int t = s;
    for (; t + 4 <= e; t += 4) {
        a0 += S[(size_t)(t + 0) * DOUT + col];
        a1 += S[(size_t)(t + 1) * DOUT + col];
        a2 += S[(size_t)(t + 2) * DOUT + col];
        a3 += S[(size_t)(t + 3) * DOUT + col];
    }
    float acc = (a0 + a1) + (a2 + a3);
    for (; t < e; t++) acc += S[(size_t)t * DOUT + col];

    out[(size_t)g * DOUT + col] = acc;
}

extern "C" void kernel_launch(void* const* d_in, const int* in_sizes, int n_in,
                              void* d_out, int out_size)
{
    const float* hidden   = (const float*)d_in[0];  // [B*S, H] flattened
    const float* W1       = (const float*)d_in[1];  // [D_MID, H]
    const float* b1       = (const float*)d_in[2];  // [D_MID]
    const float* W2       = (const float*)d_in[3];  // [D_OUT, D_MID]
    const float* b2       = (const float*)d_in[4];  // [D_OUT]
    const int*   flat_idx = (const int*)d_in[5];    // [N_TOK]
    const int*   seg      = (const int*)d_in[6];    // [N_TOK] sorted
    float*       out      = (float*)d_out;          // [N_IMG, D_OUT]

    const int n_tok = in_sizes[5];
    const int n_img = out_size / DOUT;

    float *hbuf, *sbuf;
    cudaGetSymbolAddress((void**)&hbuf, g_H);
    cudaGetSymbolAddress((void**)&sbuf, g_S);

    // GEMM1 + bias + mish: [n_tok, 2048] x [1024, 2048]^T -> [n_tok, 1024]
    dim3 g1(n_tok / 128, DMID / 128);
    gemm_bias_act<2048, true, true><<<g1, 256>>>(hidden, W1, b1, flat_idx, hbuf, DMID);

    // GEMM2 + bias: [n_tok, 1024] x [256, 1024]^T -> [n_tok, 256]
    dim3 g2(n_tok / 128, DOUT / 128);
    gemm_bias_act<1024, false, false><<<g2, 256>>>(hbuf, W2, b2, nullptr, sbuf, DOUT);

    // Deterministic segment pooling -> [n_img, 256]
    pool_kernel<<<n_img, 256>>>(sbuf, seg, n_tok, out);
}

// round 3
// speedup vs baseline: 2.7314x; 2.7314x over previous
#include <cuda_runtime.h>
#include <cuda_bf16.h>
#include <cstdint>

// ---------------------------------------------------------------------------
// VLMSpatialHead via mma.sync (HMMA bf16, base sm_103 target — tcgen05 is
// rejected by this harness's ptxas target):
//   X   = hidden[flat_idx]              [N_TOK, 2048]
//   Hm  = mish(X @ W1^T + b1)           [N_TOK, 1024]
//   S   = Hm @ W2^T + b2                [N_TOK, 256]
//   out = segment_sum(S, segment_ids)   [N_IMG, 256]
// fp32 accuracy via bf16 hi/lo split, 3 products (hi*hi + hi*lo + lo*hi).
// ---------------------------------------------------------------------------

#define NTOK_MAX 32768
#define HDIM     2048
#define DMID     1024
#define DOUT     256
#define PCHUNK   16

// ---------------- scratch (device globals; no allocs) ----------------
__device__ __align__(256) __nv_bfloat16 g_Xhi[(size_t)NTOK_MAX * HDIM];
__device__ __align__(256) __nv_bfloat16 g_Xlo[(size_t)NTOK_MAX * HDIM];
__device__ __align__(256) __nv_bfloat16 g_W1hi[(size_t)DMID * HDIM];
__device__ __align__(256) __nv_bfloat16 g_W1lo[(size_t)DMID * HDIM];
__device__ __align__(256) __nv_bfloat16 g_W2hi[(size_t)DOUT * DMID];
__device__ __align__(256) __nv_bfloat16 g_W2lo[(size_t)DOUT * DMID];
__device__ __align__(256) __nv_bfloat16 g_Hhi[(size_t)NTOK_MAX * DMID];
__device__ __align__(256) __nv_bfloat16 g_Hlo[(size_t)NTOK_MAX * DMID];
__device__ __align__(256) float         g_S  [(size_t)NTOK_MAX * DOUT];
__device__ __align__(256) float         g_P  [64 * PCHUNK * DOUT];

// ---------------- helpers ----------------
__device__ __forceinline__ uint32_t smem_u32(const void* p) {
    uint32_t a;
    asm("{ .reg .u64 t; cvta.to.shared.u64 t, %1; cvt.u32.u64 %0, t; }" : "=r"(a) : "l"(p));
    return a;
}
__device__ __forceinline__ void cp16(uint32_t saddr, const void* gaddr) {
    asm volatile("cp.async.cg.shared.global [%0], [%1], 16;" :: "r"(saddr), "l"(gaddr));
}
#define CP_COMMIT() asm volatile("cp.async.commit_group;" ::: "memory")
#define CP_WAIT2()  asm volatile("cp.async.wait_group 2;"  ::: "memory")

#define LDSM4(r0, r1, r2, r3, a) \
    asm volatile("ldmatrix.sync.aligned.m8n8.x4.shared.b16 {%0,%1,%2,%3}, [%4];" \
                 : "=r"(r0), "=r"(r1), "=r"(r2), "=r"(r3) : "r"(a))

#define MMA16816(c, a, b) \
    asm volatile("mma.sync.aligned.m16n8k16.row.col.f32.bf16.bf16.f32 " \
                 "{%0,%1,%2,%3}, {%4,%5,%6,%7}, {%8,%9}, {%0,%1,%2,%3};" \
                 : "+f"((c)[0]), "+f"((c)[1]), "+f"((c)[2]), "+f"((c)[3]) \
                 : "r"((a)[0]), "r"((a)[1]), "r"((a)[2]), "r"((a)[3]), \
                   "r"((b)[0]), "r"((b)[1]))

// swizzled smem offset: 128 rows x 64B, quad XOR keeps ldmatrix conflict-free
__device__ __forceinline__ uint32_t swz(int r, int q) {
    return (uint32_t)(r * 64 + ((q ^ ((r >> 1) & 3)) << 4));
}
__device__ __forceinline__ float mish_fast(float x) {
    float t = __expf(fminf(x, 20.0f));
    float u = t * (t + 2.0f);
    return x * __fdividef(u, u + 2.0f);
}

// ---------------- fp32 -> bf16 hi/lo split (optional gather + pad) ----
__global__ void __launch_bounds__(256)
split_bf16(const float* __restrict__ src, const int* __restrict__ gidx,
           int rows_valid, long long total4, int K,
           __nv_bfloat16* __restrict__ hi, __nv_bfloat16* __restrict__ lo)
{
    long long i = (long long)blockIdx.x * 256 + threadIdx.x;
    if (i >= total4) return;
    int k4 = K >> 2;
    int row = (int)(i / k4);
    int c   = (int)(i % k4);
    float4 v = make_float4(0.f, 0.f, 0.f, 0.f);
    if (row < rows_valid) {
        size_t srow = gidx ? (size_t)gidx[row] : (size_t)row;
        v = *(const float4*)(src + srow * (size_t)K + (size_t)c * 4);
    }
    float vv[4] = {v.x, v.y, v.z, v.w};
    __nv_bfloat16 h[4], l[4];
    #pragma unroll
    for (int j = 0; j < 4; j++) {
        h[j] = __float2bfloat16(vv[j]);
        l[j] = __float2bfloat16(vv[j] - __bfloat162float(h[j]));
    }
    __nv_bfloat162 h0 = __halves2bfloat162(h[0], h[1]);
    __nv_bfloat162 h1 = __halves2bfloat162(h[2], h[3]);
    __nv_bfloat162 l0 = __halves2bfloat162(l[0], l[1]);
    __nv_bfloat162 l1 = __halves2bfloat162(l[2], l[3]);
    uint2 hp, lp;
    hp.x = *(uint32_t*)&h0; hp.y = *(uint32_t*)&h1;
    lp.x = *(uint32_t*)&l0; lp.y = *(uint32_t*)&l1;
    *(uint2*)(hi + i * 4) = hp;
    *(uint2*)(lo + i * 4) = lp;
}

// ---------------- HMMA GEMM: 128x128 CTA tile, BK=32, 4-stage cp.async ----
// Stage layout (32KB): [Ahi 8K][Alo 8K][Whi 8K][Wlo 8K], each 128 rows x 64B.
#define STAGE_B   32768
#define GEMM_SMEM (4 * STAGE_B)

template<int KD, bool MISH>
__global__ void __launch_bounds__(256, 1)
mma_gemm(const __nv_bfloat16* __restrict__ Ahi, const __nv_bfloat16* __restrict__ Alo,
         const __nv_bfloat16* __restrict__ Whi, const __nv_bfloat16* __restrict__ Wlo,
         const float* __restrict__ bias,
         __nv_bfloat16* __restrict__ OHi, __nv_bfloat16* __restrict__ OLo,
         float* __restrict__ OF, int ldo)
{
    extern __shared__ __align__(128) char sm[];
    const uint32_t sbase = smem_u32(sm);
    const int tid  = threadIdx.x;
    const int lane = tid & 31;
    const int warp = tid >> 5;
    const int wm   = warp >> 2;   // 0..1 -> 64 rows
    const int wn   = warp & 3;    // 0..3 -> 32 cols
    const int bm   = blockIdx.y * 128;
    const int bn   = blockIdx.x * 128;

    constexpr int NCH   = KD / 32;       // K chunks of 32 bf16 (64B)
    const int krow4     = KD / 8;        // row stride in uint4

    const uint4* srcA[2] = { (const uint4*)Ahi, (const uint4*)Alo };
    const uint4* srcW[2] = { (const uint4*)Whi, (const uint4*)Wlo };

    // r/q for this thread's cp.async chunks (2 per matrix per stage)
    // e = tid + it*256 ; r = e>>2 (row), q = e&3 (16B quad)
    auto load_stage = [&](int ch) {
        const uint32_t st = sbase + (uint32_t)(ch & 3) * STAGE_B;
        #pragma unroll
        for (int m = 0; m < 2; m++) {
            #pragma unroll
            for (int it = 0; it < 2; it++) {
                int e = tid + it * 256, r = e >> 2, q = e & 3;
                cp16(st + m * 8192 + swz(r, q),
                     srcA[m] + (size_t)(bm + r) * krow4 + ch * 4 + q);
            }
        }
        #pragma unroll
        for (int m = 0; m < 2; m++) {
            #pragma unroll
            for (int it = 0; it < 2; it++) {
                int e = tid + it * 256, r = e >> 2, q = e & 3;
                cp16(st + 16384 + m * 8192 + swz(r, q),
                     srcW[m] + (size_t)(bn + r) * krow4 + ch * 4 + q);
            }
        }
    };

    float acc[4][4][4];
    #pragma unroll
    for (int i = 0; i < 4; i++)
        #pragma unroll
        for (int j = 0; j < 4; j++)
            #pragma unroll
            for (int k = 0; k < 4; k++) acc[i][j][k] = 0.0f;

    // prologue: 3 stages in flight
    load_stage(0); CP_COMMIT();
    load_stage(1); CP_COMMIT();
    load_stage(2); CP_COMMIT();

    for (int i = 0; i < NCH; ++i) {
        CP_WAIT2();
        __syncthreads();
        const uint32_t st = sbase + (uint32_t)(i & 3) * STAGE_B;

        #pragma unroll
        for (int ks = 0; ks < 2; ks++) {           // two K16 steps per chunk
            const int qb = ks * 2 + (lane >> 4);   // quad for this lane

            uint32_t ah[4][4], al[4][4];
            #pragma unroll
            for (int mt = 0; mt < 4; mt++) {
                int r = wm * 64 + mt * 16 + (lane & 15);
                uint32_t off = swz(r, qb);
                LDSM4(ah[mt][0], ah[mt][1], ah[mt][2], ah[mt][3], st + off);
                LDSM4(al[mt][0], al[mt][1], al[mt][2], al[mt][3], st + 8192 + off);
            }
            uint32_t bh[4][2], bl[4][2];
            #pragma unroll
            for (int p = 0; p < 2; p++) {
                int r = wn * 32 + p * 16 + (lane & 15);
                uint32_t off = swz(r, qb);
                uint32_t t0, t1, t2, t3;
                LDSM4(t0, t1, t2, t3, st + 16384 + off);
                bh[p*2][0] = t0; bh[p*2+1][0] = t1; bh[p*2][1] = t2; bh[p*2+1][1] = t3;
                LDSM4(t0, t1, t2, t3, st + 24576 + off);
                bl[p*2][0] = t0; bl[p*2+1][0] = t1; bl[p*2][1] = t2; bl[p*2+1][1] = t3;
            }
            #pragma unroll
            for (int mt = 0; mt < 4; mt++)
                #pragma unroll
                for (int nt = 0; nt < 4; nt++) {
                    MMA16816(acc[mt][nt], ah[mt], bh[nt]);
                    MMA16816(acc[mt][nt], ah[mt], bl[nt]);
                    MMA16816(acc[mt][nt], al[mt], bh[nt]);
                }
        }

        int nxt = i + 3;
        if (nxt < NCH) load_stage(nxt);
        CP_COMMIT();
    }

    // -------- epilogue --------
    const int g  = lane >> 2;
    const int c2 = (lane & 3) * 2;
    #pragma unroll
    for (int nt = 0; nt < 4; nt++) {
        const int col = bn + wn * 32 + nt * 8 + c2;
        float2 bv = __ldg((const float2*)(bias + col));
        #pragma unroll
        for (int mt = 0; mt < 4; mt++) {
            const int row0 = bm + wm * 64 + mt * 16 + g;
            float v0 = acc[mt][nt][0] + bv.x;
            float v1 = acc[mt][nt][1] + bv.y;
            float v2 = acc[mt][nt][2] + bv.x;
            float v3 = acc[mt][nt][3] + bv.y;
            if (MISH) {
                v0 = mish_fast(v0); v1 = mish_fast(v1);
                v2 = mish_fast(v2); v3 = mish_fast(v3);
                __nv_bfloat16 h0 = __float2bfloat16(v0), h1 = __float2bfloat16(v1);
                __nv_bfloat16 h2 = __float2bfloat16(v2), h3 = __float2bfloat16(v3);
                __nv_bfloat162 hv0 = __halves2bfloat162(h0, h1);
                __nv_bfloat162 hv1 = __halves2bfloat162(h2, h3);
                __nv_bfloat162 lv0 = __halves2bfloat162(
                    __float2bfloat16(v0 - __bfloat162float(h0)),
                    __float2bfloat16(v1 - __bfloat162float(h1)));
                __nv_bfloat162 lv1 = __halves2bfloat162(
                    __float2bfloat16(v2 - __bfloat162float(h2)),
                    __float2bfloat16(v3 - __bfloat162float(h3)));
                *(__nv_bfloat162*)(OHi + (size_t)row0 * ldo + col)       = hv0;
                *(__nv_bfloat162*)(OHi + (size_t)(row0 + 8) * ldo + col) = hv1;
                *(__nv_bfloat162*)(OLo + (size_t)row0 * ldo + col)       = lv0;
                *(__nv_bfloat162*)(OLo + (size_t)(row0 + 8) * ldo + col) = lv1;
            } else {
                *(float2*)(OF + (size_t)row0 * ldo + col)       = make_float2(v0, v1);
                *(float2*)(OF + (size_t)(row0 + 8) * ldo + col) = make_float2(v2, v3);
            }
        }
    }
}

// ---------------- deterministic 2-phase segment pooling ----------------
__global__ void __launch_bounds__(1024)
pool_partial(const float* __restrict__ S, const int* __restrict__ seg,
             int n_tok, float* __restrict__ P)
{
    const int gseg = blockIdx.x;
    const int sub  = threadIdx.x >> 8;              // 0..3
    const int col  = threadIdx.x & 255;
    const int chunk = blockIdx.y * 4 + sub;         // 0..PCHUNK-1

    int lo = 0, hi = n_tok;
    while (lo < hi) { int m = (lo + hi) >> 1; if (seg[m] < gseg) lo = m + 1; else hi = m; }
    const int s = lo;
    lo = s; hi = n_tok;
    while (lo < hi) { int m = (lo + hi) >> 1; if (seg[m] < gseg + 1) lo = m + 1; else hi = m; }
    const int e = lo;

    const int len = e - s;
    const int L = (len + PCHUNK - 1) / PCHUNK;
    const int cs = s + chunk * L;
    const int ce = min(cs + L, e);

    float a0 = 0.f, a1 = 0.f, a2 = 0.f, a3 = 0.f;
    int t = cs;
    for (; t + 4 <= ce; t += 4) {
        a0 += S[(size_t)(t + 0) * DOUT + col];
        a1 += S[(size_t)(t + 1) * DOUT + col];
        a2 += S[(size_t)(t + 2) * DOUT + col];
        a3 += S[(size_t)(t + 3) * DOUT + col];
    }
    float acc = (a0 + a1) + (a2 + a3);
    for (; t < ce; t++) acc += S[(size_t)t * DOUT + col];
    P[((size_t)gseg * PCHUNK + chunk) * DOUT + col] = acc;
}

__global__ void __launch_bounds__(256)
pool_final(const float* __restrict__ P, float* __restrict__ out)
{
    const int gseg = blockIdx.x, col = threadIdx.x;
    float acc = 0.f;
    #pragma unroll
    for (int c = 0; c < PCHUNK; c++)
        acc += P[((size_t)gseg * PCHUNK + c) * DOUT + col];
    out[(size_t)gseg * DOUT + col] = acc;
}

// ---------------- launch ----------------
extern "C" void kernel_launch(void* const* d_in, const int* in_sizes, int n_in,
                              void* d_out, int out_size)
{
    const float* hidden   = (const float*)d_in[0];
    const float* W1       = (const float*)d_in[1];
    const float* b1       = (const float*)d_in[2];
    const float* W2       = (const float*)d_in[3];
    const float* b2       = (const float*)d_in[4];
    const int*   flat_idx = (const int*)d_in[5];
    const int*   seg      = (const int*)d_in[6];
    float*       out      = (float*)d_out;

    const int n_tok = in_sizes[5];
    const int n_img = out_size / DOUT;
    const int mpad  = ((n_tok + 127) / 128) * 128;

    __nv_bfloat16 *xhi, *xlo, *w1hi, *w1lo, *w2hi, *w2lo, *hhi, *hlo;
    float *sbuf, *pbuf;
    cudaGetSymbolAddress((void**)&xhi,  g_Xhi);
    cudaGetSymbolAddress((void**)&xlo,  g_Xlo);
    cudaGetSymbolAddress((void**)&w1hi, g_W1hi);
    cudaGetSymbolAddress((void**)&w1lo, g_W1lo);
    cudaGetSymbolAddress((void**)&w2hi, g_W2hi);
    cudaGetSymbolAddress((void**)&w2lo, g_W2lo);
    cudaGetSymbolAddress((void**)&hhi,  g_Hhi);
    cudaGetSymbolAddress((void**)&hlo,  g_Hlo);
    cudaGetSymbolAddress((void**)&sbuf, g_S);
    cudaGetSymbolAddress((void**)&pbuf, g_P);

    cudaFuncSetAttribute(mma_gemm<HDIM, true>,
                         cudaFuncAttributeMaxDynamicSharedMemorySize, GEMM_SMEM);
    cudaFuncSetAttribute(mma_gemm<DMID, false>,
                         cudaFuncAttributeMaxDynamicSharedMemorySize, GEMM_SMEM);

    // 1) splits
    {
        long long t4 = (long long)mpad * HDIM / 4;
        split_bf16<<<(unsigned)((t4 + 255) / 256), 256>>>(hidden, flat_idx, n_tok, t4, HDIM, xhi, xlo);
        long long w1t = (long long)DMID * HDIM / 4;
        split_bf16<<<(unsigned)((w1t + 255) / 256), 256>>>(W1, nullptr, DMID, w1t, HDIM, w1hi, w1lo);
        long long w2t = (long long)DOUT * DMID / 4;
        split_bf16<<<(unsigned)((w2t + 255) / 256), 256>>>(W2, nullptr, DOUT, w2t, DMID, w2hi, w2lo);
    }
    // 2) GEMM1 + bias + mish -> H (bf16 hi/lo)
    {
        dim3 g(DMID / 128, mpad / 128);
        mma_gemm<HDIM, true><<<g, 256, GEMM_SMEM>>>(xhi, xlo, w1hi, w1lo, b1,
                                                    hhi, hlo, nullptr, DMID);
    }
    // 3) GEMM2 + bias -> S (fp32)
    {
        dim3 g(DOUT / 128, mpad / 128);
        mma_gemm<DMID, false><<<g, 256, GEMM_SMEM>>>(hhi, hlo, w2hi, w2lo, b2,
                                                     nullptr, nullptr, sbuf, DOUT);
    }
    // 4) pooling (2-phase deterministic)
    {
        dim3 gp(n_img, PCHUNK / 4);
        pool_partial<<<gp, 1024>>>(sbuf, seg, n_tok, pbuf);
        pool_final<<<n_img, 256>>>(pbuf, out);
    }
}

// round 4
// speedup vs baseline: 2.9227x; 1.0700x over previous
#include <cuda_runtime.h>
#include <cuda_bf16.h>
#include <cstdint>

// ---------------------------------------------------------------------------
// VLMSpatialHead via mma.sync (HMMA bf16) on sm_103:
//   X   = hidden[flat_idx]              [N_TOK, 2048]
//   Hm  = mish(X @ W1^T + b1)           [N_TOK, 1024]
//   S   = Hm @ W2^T + b2                [N_TOK, 256]
//   out = segment_sum(S, segment_ids)   [N_IMG, 256]
// fp32-class accuracy via bf16 hi/lo split, 3 products (hh + hl + lh).
// R4: product-major MMA ordering (breaks acc RAW chains), BK=64 + 3-stage
//     cp.async ring, hoisted addressing.
// ---------------------------------------------------------------------------

#define NTOK_MAX 32768
#define HDIM     2048
#define DMID     1024
#define DOUT     256
#define PCHUNK   16

// ---------------- scratch (device globals; no allocs) ----------------
__device__ __align__(256) __nv_bfloat16 g_Xhi[(size_t)NTOK_MAX * HDIM];
__device__ __align__(256) __nv_bfloat16 g_Xlo[(size_t)NTOK_MAX * HDIM];
__device__ __align__(256) __nv_bfloat16 g_W1hi[(size_t)DMID * HDIM];
__device__ __align__(256) __nv_bfloat16 g_W1lo[(size_t)DMID * HDIM];
__device__ __align__(256) __nv_bfloat16 g_W2hi[(size_t)DOUT * DMID];
__device__ __align__(256) __nv_bfloat16 g_W2lo[(size_t)DOUT * DMID];
__device__ __align__(256) __nv_bfloat16 g_Hhi[(size_t)NTOK_MAX * DMID];
__device__ __align__(256) __nv_bfloat16 g_Hlo[(size_t)NTOK_MAX * DMID];
__device__ __align__(256) float         g_S  [(size_t)NTOK_MAX * DOUT];
__device__ __align__(256) float         g_P  [64 * PCHUNK * DOUT];

// ---------------- helpers ----------------
__device__ __forceinline__ uint32_t smem_u32(const void* p) {
    uint32_t a;
    asm("{ .reg .u64 t; cvta.to.shared.u64 t, %1; cvt.u32.u64 %0, t; }" : "=r"(a) : "l"(p));
    return a;
}
__device__ __forceinline__ void cp16(uint32_t saddr, const void* gaddr) {
    asm volatile("cp.async.cg.shared.global [%0], [%1], 16;" :: "r"(saddr), "l"(gaddr));
}
#define CP_COMMIT() asm volatile("cp.async.commit_group;" ::: "memory")
#define CP_WAIT1()  asm volatile("cp.async.wait_group 1;"  ::: "memory")

#define LDSM4(r0, r1, r2, r3, a) \
    asm volatile("ldmatrix.sync.aligned.m8n8.x4.shared.b16 {%0,%1,%2,%3}, [%4];" \
                 : "=r"(r0), "=r"(r1), "=r"(r2), "=r"(r3) : "r"(a))

#define MMA16816(c, a, b) \
    asm volatile("mma.sync.aligned.m16n8k16.row.col.f32.bf16.bf16.f32 " \
                 "{%0,%1,%2,%3}, {%4,%5,%6,%7}, {%8,%9}, {%0,%1,%2,%3};" \
                 : "+f"((c)[0]), "+f"((c)[1]), "+f"((c)[2]), "+f"((c)[3]) \
                 : "r"((a)[0]), "r"((a)[1]), "r"((a)[2]), "r"((a)[3]), \
                   "r"((b)[0]), "r"((b)[1]))

__device__ __forceinline__ float mish_fast(float x) {
    float t = __expf(fminf(x, 20.0f));
    float u = t * (t + 2.0f);
    return x * __fdividef(u, u + 2.0f);
}

// ---------------- fp32 -> bf16 hi/lo split (optional gather + pad) ----
__global__ void __launch_bounds__(256)
split_bf16(const float* __restrict__ src, const int* __restrict__ gidx,
           int rows_valid, long long total4, int K,
           __nv_bfloat16* __restrict__ hi, __nv_bfloat16* __restrict__ lo)
{
    long long i = (long long)blockIdx.x * 256 + threadIdx.x;
    if (i >= total4) return;
    int k4 = K >> 2;
    int row = (int)(i / k4);
    int c   = (int)(i % k4);
    float4 v = make_float4(0.f, 0.f, 0.f, 0.f);
    if (row < rows_valid) {
        size_t srow = gidx ? (size_t)gidx[row] : (size_t)row;
        v = *(const float4*)(src + srow * (size_t)K + (size_t)c * 4);
    }
    float vv[4] = {v.x, v.y, v.z, v.w};
    __nv_bfloat16 h[4], l[4];
    #pragma unroll
    for (int j = 0; j < 4; j++) {
        h[j] = __float2bfloat16(vv[j]);
        l[j] = __float2bfloat16(vv[j] - __bfloat162float(h[j]));
    }
    __nv_bfloat162 h0 = __halves2bfloat162(h[0], h[1]);
    __nv_bfloat162 h1 = __halves2bfloat162(h[2], h[3]);
    __nv_bfloat162 l0 = __halves2bfloat162(l[0], l[1]);
    __nv_bfloat162 l1 = __halves2bfloat162(l[2], l[3]);
    uint2 hp, lp;
    hp.x = *(uint32_t*)&h0; hp.y = *(uint32_t*)&h1;
    lp.x = *(uint32_t*)&l0; lp.y = *(uint32_t*)&l1;
    *(uint2*)(hi + i * 4) = hp;
    *(uint2*)(lo + i * 4) = lp;
}

// ---------------- HMMA GEMM: 128x128 CTA tile, BK=64, 3-stage cp.async ----
// Stage layout (64KB): [Ahi 16K][Alo 16K][Whi 16K][Wlo 16K],
// each 128 rows x 128B (full SW128 swizzle: quad ^= row&7).
#define STAGE_B   65536
#define GEMM_SMEM (3 * STAGE_B)

template<int KD, bool MISH>
__global__ void __launch_bounds__(256, 1)
mma_gemm(const __nv_bfloat16* __restrict__ Ahi, const __nv_bfloat16* __restrict__ Alo,
         const __nv_bfloat16* __restrict__ Whi, const __nv_bfloat16* __restrict__ Wlo,
         const float* __restrict__ bias,
         __nv_bfloat16* __restrict__ OHi, __nv_bfloat16* __restrict__ OLo,
         float* __restrict__ OF, int ldo)
{
    extern __shared__ __align__(128) char sm[];
    const uint32_t sbase = smem_u32(sm);
    const int tid  = threadIdx.x;
    const int lane = tid & 31;
    const int warp = tid >> 5;
    const int wm   = warp >> 2;   // 0..1 -> 64 rows
    const int wn   = warp & 3;    // 0..3 -> 32 cols
    const int bm   = blockIdx.y * 128;
    const int bn   = blockIdx.x * 128;

    constexpr int NCH = KD / 64;        // K chunks of 64 bf16 (128B)
    const int krow4   = KD / 8;         // row stride in uint4

    // ---- hoisted cp.async addressing: 16 chunks/thread/stage ----
    // per matrix: 128 rows x 8 quads = 1024 chunks -> 4 per thread
    const uint4* gp[16];
    uint32_t     so[16];
    {
        const uint4* srcs[4] = { (const uint4*)Ahi, (const uint4*)Alo,
                                 (const uint4*)Whi, (const uint4*)Wlo };
        #pragma unroll
        for (int m = 0; m < 4; m++) {
            const int rb = (m < 2) ? bm : bn;
            #pragma unroll
            for (int it = 0; it < 4; it++) {
                int e = tid + it * 256, r = e >> 3, q = e & 7;
                int j = m * 4 + it;
                gp[j] = srcs[m] + (size_t)(rb + r) * krow4 + q;
                so[j] = (uint32_t)(m * 16384 + r * 128 + ((q ^ (r & 7)) << 4));
            }
        }
    }
    // ---- hoisted ldmatrix row bases ----
    uint32_t aRowOff[4]; int aX7[4];
    #pragma unroll
    for (int mt = 0; mt < 4; mt++) {
        int r = wm * 64 + mt * 16 + (lane & 15);
        aRowOff[mt] = (uint32_t)(r * 128); aX7[mt] = r & 7;
    }
    uint32_t bRowOff[2]; int bX7[2];
    #pragma unroll
    for (int p = 0; p < 2; p++) {
        int r = wn * 32 + p * 16 + (lane & 15);
        bRowOff[p] = (uint32_t)(r * 128); bX7[p] = r & 7;
    }
    const int lh = lane >> 4;

    float acc[4][4][4];
    #pragma unroll
    for (int i = 0; i < 4; i++)
        #pragma unroll
        for (int j = 0; j < 4; j++)
            #pragma unroll
            for (int k = 0; k < 4; k++) acc[i][j][k] = 0.0f;

    auto load_stage = [&](int ch, uint32_t st) {
        #pragma unroll
        for (int j = 0; j < 16; j++) cp16(st + so[j], gp[j] + ch * 8);
    };

    // prologue: 2 stages in flight
    load_stage(0, sbase);           CP_COMMIT();
    if (NCH > 1) load_stage(1, sbase + STAGE_B);
    CP_COMMIT();

    int slot = 0;
    for (int i = 0; i < NCH; ++i) {
        CP_WAIT1();
        __syncthreads();
        const uint32_t st = sbase + (uint32_t)slot * STAGE_B;

        #pragma unroll
        for (int ks = 0; ks < 4; ks++) {           // four K16 steps per chunk
            const int qb = ks * 2 + lh;

            uint32_t ah[4][4], al[4][4];
            #pragma unroll
            for (int mt = 0; mt < 4; mt++) {
                uint32_t offh = st +         aRowOff[mt] + (uint32_t)((qb ^ aX7[mt]) << 4);
                uint32_t offl = st + 16384 + aRowOff[mt] + (uint32_t)((qb ^ aX7[mt]) << 4);
                LDSM4(ah[mt][0], ah[mt][1], ah[mt][2], ah[mt][3], offh);
                LDSM4(al[mt][0], al[mt][1], al[mt][2], al[mt][3], offl);
            }
            uint32_t bh[4][2], bl[4][2];
            #pragma unroll
            for (int p = 0; p < 2; p++) {
                uint32_t off = bRowOff[p] + (uint32_t)((qb ^ bX7[p]) << 4);
                uint32_t t0, t1, t2, t3;
                LDSM4(t0, t1, t2, t3, st + 32768 + off);
                bh[p*2][0] = t0; bh[p*2+1][0] = t1; bh[p*2][1] = t2; bh[p*2+1][1] = t3;
                LDSM4(t0, t1, t2, t3, st + 49152 + off);
                bl[p*2][0] = t0; bl[p*2+1][0] = t1; bl[p*2][1] = t2; bl[p*2+1][1] = t3;
            }
            // product-major: 16 independent accumulators between reuse
            #pragma unroll
            for (int mt = 0; mt < 4; mt++)
                #pragma unroll
                for (int nt = 0; nt < 4; nt++)
                    MMA16816(acc[mt][nt], ah[mt], bh[nt]);
            #pragma unroll
            for (int mt = 0; mt < 4; mt++)
                #pragma unroll
                for (int nt = 0; nt < 4; nt++)
                    MMA16816(acc[mt][nt], ah[mt], bl[nt]);
            #pragma unroll
            for (int mt = 0; mt < 4; mt++)
                #pragma unroll
                for (int nt = 0; nt < 4; nt++)
                    MMA16816(acc[mt][nt], al[mt], bh[nt]);
        }

        int nxt = i + 2;
        if (nxt < NCH) {
            int ns = slot + 2; if (ns >= 3) ns -= 3;
            load_stage(nxt, sbase + (uint32_t)ns * STAGE_B);
        }
        CP_COMMIT();
        if (++slot == 3) slot = 0;
    }

    // -------- epilogue --------
    const int g  = lane >> 2;
    const int c2 = (lane & 3) * 2;
    #pragma unroll
    for (int nt = 0; nt < 4; nt++) {
        const int col = bn + wn * 32 + nt * 8 + c2;
        float2 bv = __ldg((const float2*)(bias + col));
        #pragma unroll
        for (int mt = 0; mt < 4; mt++) {
            const int row0 = bm + wm * 64 + mt * 16 + g;
            float v0 = acc[mt][nt][0] + bv.x;
            float v1 = acc[mt][nt][1] + bv.y;
            float v2 = acc[mt][nt][2] + bv.x;
            float v3 = acc[mt][nt][3] + bv.y;
            if (MISH) {
                v0 = mish_fast(v0); v1 = mish_fast(v1);
                v2 = mish_fast(v2); v3 = mish_fast(v3);
                __nv_bfloat16 h0 = __float2bfloat16(v0), h1 = __float2bfloat16(v1);
                __nv_bfloat16 h2 = __float2bfloat16(v2), h3 = __float2bfloat16(v3);
                __nv_bfloat162 hv0 = __halves2bfloat162(h0, h1);
                __nv_bfloat162 hv1 = __halves2bfloat162(h2, h3);
                __nv_bfloat162 lv0 = __halves2bfloat162(
                    __float2bfloat16(v0 - __bfloat162float(h0)),
                    __float2bfloat16(v1 - __bfloat162float(h1)));
                __nv_bfloat162 lv1 = __halves2bfloat162(
                    __float2bfloat16(v2 - __bfloat162float(h2)),
                    __float2bfloat16(v3 - __bfloat162float(h3)));
                *(__nv_bfloat162*)(OHi + (size_t)row0 * ldo + col)       = hv0;
                *(__nv_bfloat162*)(OHi + (size_t)(row0 + 8) * ldo + col) = hv1;
                *(__nv_bfloat162*)(OLo + (size_t)row0 * ldo + col)       = lv0;
                *(__nv_bfloat162*)(OLo + (size_t)(row0 + 8) * ldo + col) = lv1;
            } else {
                *(float2*)(OF + (size_t)row0 * ldo + col)       = make_float2(v0, v1);
                *(float2*)(OF + (size_t)(row0 + 8) * ldo + col) = make_float2(v2, v3);
            }
        }
    }
}

// ---------------- deterministic 2-phase segment pooling ----------------
__global__ void __launch_bounds__(1024)
pool_partial(const float* __restrict__ S, const int* __restrict__ seg,
             int n_tok, float* __restrict__ P)
{
    const int gseg = blockIdx.x;
    const int sub  = threadIdx.x >> 8;
    const int col  = threadIdx.x & 255;
    const int chunk = blockIdx.y * 4 + sub;

    int lo = 0, hi = n_tok;
    while (lo < hi) { int m = (lo + hi) >> 1; if (seg[m] < gseg) lo = m + 1; else hi = m; }
    const int s = lo;
    lo = s; hi = n_tok;
    while (lo < hi) { int m = (lo + hi) >> 1; if (seg[m] < gseg + 1) lo = m + 1; else hi = m; }
    const int e = lo;

    const int len = e - s;
    const int L = (len + PCHUNK - 1) / PCHUNK;
    const int cs = s + chunk * L;
    const int ce = min(cs + L, e);

    float a0 = 0.f, a1 = 0.f, a2 = 0.f, a3 = 0.f;
    int t = cs;
    for (; t + 4 <= ce; t += 4) {
        a0 += S[(size_t)(t + 0) * DOUT + col];
        a1 += S[(size_t)(t + 1) * DOUT + col];
        a2 += S[(size_t)(t + 2) * DOUT + col];
        a3 += S[(size_t)(t + 3) * DOUT + col];
    }
    float acc = (a0 + a1) + (a2 + a3);
    for (; t < ce; t++) acc += S[(size_t)t * DOUT + col];
    P[((size_t)gseg * PCHUNK + chunk) * DOUT + col] = acc;
}

__global__ void __launch_bounds__(256)
pool_final(const float* __restrict__ P, float* __restrict__ out)
{
    const int gseg = blockIdx.x, col = threadIdx.x;
    float acc = 0.f;
    #pragma unroll
    for (int c = 0; c < PCHUNK; c++)
        acc += P[((size_t)gseg * PCHUNK + c) * DOUT + col];
    out[(size_t)gseg * DOUT + col] = acc;
}

// ---------------- launch ----------------
extern "C" void kernel_launch(void* const* d_in, const int* in_sizes, int n_in,
                              void* d_out, int out_size)
{
    const float* hidden   = (const float*)d_in[0];
    const float* W1       = (const float*)d_in[1];
    const float* b1       = (const float*)d_in[2];
    const float* W2       = (const float*)d_in[3];
    const float* b2       = (const float*)d_in[4];
    const int*   flat_idx = (const int*)d_in[5];
    const int*   seg      = (const int*)d_in[6];
    float*       out      = (float*)d_out;

    const int n_tok = in_sizes[5];
    const int n_img = out_size / DOUT;
    const int mpad  = ((n_tok + 127) / 128) * 128;

    __nv_bfloat16 *xhi, *xlo, *w1hi, *w1lo, *w2hi, *w2lo, *hhi, *hlo;
    float *sbuf, *pbuf;
    cudaGetSymbolAddress((void**)&xhi,  g_Xhi);
    cudaGetSymbolAddress((void**)&xlo,  g_Xlo);
    cudaGetSymbolAddress((void**)&w1hi, g_W1hi);
    cudaGetSymbolAddress((void**)&w1lo, g_W1lo);
    cudaGetSymbolAddress((void**)&w2hi, g_W2hi);
    cudaGetSymbolAddress((void**)&w2lo, g_W2lo);
    cudaGetSymbolAddress((void**)&hhi,  g_Hhi);
    cudaGetSymbolAddress((void**)&hlo,  g_Hlo);
    cudaGetSymbolAddress((void**)&sbuf, g_S);
    cudaGetSymbolAddress((void**)&pbuf, g_P);

    cudaFuncSetAttribute(mma_gemm<HDIM, true>,
                         cudaFuncAttributeMaxDynamicSharedMemorySize, GEMM_SMEM);
    cudaFuncSetAttribute(mma_gemm<DMID, false>,
                         cudaFuncAttributeMaxDynamicSharedMemorySize, GEMM_SMEM);

    // 1) splits
    {
        long long t4 = (long long)mpad * HDIM / 4;
        split_bf16<<<(unsigned)((t4 + 255) / 256), 256>>>(hidden, flat_idx, n_tok, t4, HDIM, xhi, xlo);
        long long w1t = (long long)DMID * HDIM / 4;
        split_bf16<<<(unsigned)((w1t + 255) / 256), 256>>>(W1, nullptr, DMID, w1t, HDIM, w1hi, w1lo);
        long long w2t = (long long)DOUT * DMID / 4;
        split_bf16<<<(unsigned)((w2t + 255) / 256), 256>>>(W2, nullptr, DOUT, w2t, DMID, w2hi, w2lo);
    }
    // 2) GEMM1 + bias + mish -> H (bf16 hi/lo)
    {
        dim3 g(DMID / 128, mpad / 128);
        mma_gemm<HDIM, true><<<g, 256, GEMM_SMEM>>>(xhi, xlo, w1hi, w1lo, b1,
                                                    hhi, hlo, nullptr, DMID);
    }
    // 3) GEMM2 + bias -> S (fp32)
    {
        dim3 g(DOUT / 128, mpad / 128);
        mma_gemm<DMID, false><<<g, 256, GEMM_SMEM>>>(hhi, hlo, w2hi, w2lo, b2,
                                                     nullptr, nullptr, sbuf, DOUT);
    }
    // 4) pooling (2-phase deterministic)
    {
        dim3 gp(n_img, PCHUNK / 4);
        pool_partial<<<gp, 1024>>>(sbuf, seg, n_tok, pbuf);
        pool_final<<<n_img, 256>>>(pbuf, out);
    }
}

// round 5
// speedup vs baseline: 3.8905x; 1.3311x over previous
#include <cuda_runtime.h>
#include <cuda_fp16.h>
#include <cstdint>

// ---------------------------------------------------------------------------
// VLMSpatialHead via mma.sync (HMMA fp16) on sm_103:
//   X   = hidden[flat_idx]              [N_TOK, 2048]
//   Hm  = mish(X @ W1^T + b1)           [N_TOK, 1024]
//   S   = Hm @ W2^T + b2                [N_TOK, 256]
//   out = segment_sum(S, segment_ids)   [N_IMG, 256]
// R5: fp16 2-product scheme — activations split hi/lo fp16 (exact),
//     weights single fp16 (error 2^-12 stat) -> 2/3 the MMA work of the
//     bf16 3-product scheme. 4-stage cp.async ring, hoisted addressing.
// ---------------------------------------------------------------------------

#define NTOK_MAX 32768
#define HDIM     2048
#define DMID     1024
#define DOUT     256
#define PCHUNK   16

// ---------------- scratch (device globals; no allocs) ----------------
__device__ __align__(256) __half g_Xhi[(size_t)NTOK_MAX * HDIM];
__device__ __align__(256) __half g_Xlo[(size_t)NTOK_MAX * HDIM];
__device__ __align__(256) __half g_W1h[(size_t)DMID * HDIM];
__device__ __align__(256) __half g_W2h[(size_t)DOUT * DMID];
__device__ __align__(256) __half g_Hhi[(size_t)NTOK_MAX * DMID];
__device__ __align__(256) __half g_Hlo[(size_t)NTOK_MAX * DMID];
__device__ __align__(256) float  g_S  [(size_t)NTOK_MAX * DOUT];
__device__ __align__(256) float  g_P  [64 * PCHUNK * DOUT];

// ---------------- helpers ----------------
__device__ __forceinline__ uint32_t smem_u32(const void* p) {
    uint32_t a;
    asm("{ .reg .u64 t; cvta.to.shared.u64 t, %1; cvt.u32.u64 %0, t; }" : "=r"(a) : "l"(p));
    return a;
}
__device__ __forceinline__ void cp16(uint32_t saddr, const void* gaddr) {
    asm volatile("cp.async.cg.shared.global [%0], [%1], 16;" :: "r"(saddr), "l"(gaddr));
}
#define CP_COMMIT() asm volatile("cp.async.commit_group;" ::: "memory")
#define CP_WAIT2()  asm volatile("cp.async.wait_group 2;"  ::: "memory")

#define LDSM4(r0, r1, r2, r3, a) \
    asm volatile("ldmatrix.sync.aligned.m8n8.x4.shared.b16 {%0,%1,%2,%3}, [%4];" \
                 : "=r"(r0), "=r"(r1), "=r"(r2), "=r"(r3) : "r"(a))

#define MMA16816(c, a, b) \
    asm volatile("mma.sync.aligned.m16n8k16.row.col.f32.f16.f16.f32 " \
                 "{%0,%1,%2,%3}, {%4,%5,%6,%7}, {%8,%9}, {%0,%1,%2,%3};" \
                 : "+f"((c)[0]), "+f"((c)[1]), "+f"((c)[2]), "+f"((c)[3]) \
                 : "r"((a)[0]), "r"((a)[1]), "r"((a)[2]), "r"((a)[3]), \
                   "r"((b)[0]), "r"((b)[1]))

__device__ __forceinline__ float mish_acc(float x) {
    // mish(x) = x * u/(u+2), u = e^x (e^x + 2); precise expf for accuracy.
    float t = expf(fminf(x, 20.0f));
    float u = t * (t + 2.0f);
    return x * (u / (u + 2.0f));
}

// ---------------- fp32 -> fp16 hi/lo split (optional gather + pad) ----
// If lo == nullptr, only the hi (rounded) half is written (for weights).
__global__ void __launch_bounds__(256)
split_fp16(const float* __restrict__ src, const int* __restrict__ gidx,
           int rows_valid, long long total4, int K,
           __half* __restrict__ hi, __half* __restrict__ lo)
{
    long long i = (long long)blockIdx.x * 256 + threadIdx.x;
    if (i >= total4) return;
    int k4 = K >> 2;
    int row = (int)(i / k4);
    int c   = (int)(i % k4);
    float4 v = make_float4(0.f, 0.f, 0.f, 0.f);
    if (row < rows_valid) {
        size_t srow = gidx ? (size_t)gidx[row] : (size_t)row;
        v = *(const float4*)(src + srow * (size_t)K + (size_t)c * 4);
    }
    float vv[4] = {v.x, v.y, v.z, v.w};
    __half h[4];
    #pragma unroll
    for (int j = 0; j < 4; j++) h[j] = __float2half(vv[j]);
    __half2 h0 = __halves2half2(h[0], h[1]);
    __half2 h1 = __halves2half2(h[2], h[3]);
    uint2 hp;
    hp.x = *(uint32_t*)&h0; hp.y = *(uint32_t*)&h1;
    *(uint2*)(hi + i * 4) = hp;
    if (lo) {
        __half l[4];
        #pragma unroll
        for (int j = 0; j < 4; j++) l[j] = __float2half(vv[j] - __half2float(h[j]));
        __half2 l0 = __halves2half2(l[0], l[1]);
        __half2 l1 = __halves2half2(l[2], l[3]);
        uint2 lp;
        lp.x = *(uint32_t*)&l0; lp.y = *(uint32_t*)&l1;
        *(uint2*)(lo + i * 4) = lp;
    }
}

// ---------------- HMMA GEMM: 128x128 CTA tile, BK=64, 4-stage cp.async ----
// Stage layout (48KB): [Ahi 16K][Alo 16K][W 16K], each 128 rows x 128B,
// full SW128 swizzle (quad ^= row&7).
#define STAGE_B   49152
#define GEMM_SMEM (4 * STAGE_B)

template<int KD, bool MISH>
__global__ void __launch_bounds__(256, 1)
mma_gemm(const __half* __restrict__ Ahi, const __half* __restrict__ Alo,
         const __half* __restrict__ W,
         const float* __restrict__ bias,
         __half* __restrict__ OHi, __half* __restrict__ OLo,
         float* __restrict__ OF, int ldo)
{
    extern __shared__ __align__(128) char sm[];
    const uint32_t sbase = smem_u32(sm);
    const int tid  = threadIdx.x;
    const int lane = tid & 31;
    const int warp = tid >> 5;
    const int wm   = warp >> 2;   // 0..1 -> 64 rows
    const int wn   = warp & 3;    // 0..3 -> 32 cols
    const int bm   = blockIdx.y * 128;
    const int bn   = blockIdx.x * 128;

    constexpr int NCH = KD / 64;        // K chunks of 64 fp16 (128B)
    const int krow4   = KD / 8;         // row stride in uint4

    // ---- hoisted cp.async addressing: 12 chunks/thread/stage ----
    const uint4* gp[12];
    uint32_t     so[12];
    {
        const uint4* srcs[3] = { (const uint4*)Ahi, (const uint4*)Alo, (const uint4*)W };
        #pragma unroll
        for (int m = 0; m < 3; m++) {
            const int rb = (m < 2) ? bm : bn;
            #pragma unroll
            for (int it = 0; it < 4; it++) {
                int e = tid + it * 256, r = e >> 3, q = e & 7;
                int j = m * 4 + it;
                gp[j] = srcs[m] + (size_t)(rb + r) * krow4 + q;
                so[j] = (uint32_t)(m * 16384 + r * 128 + ((q ^ (r & 7)) << 4));
            }
        }
    }
    // ---- hoisted ldmatrix row bases ----
    uint32_t aRowOff[4]; int aX7[4];
    #pragma unroll
    for (int mt = 0; mt < 4; mt++) {
        int r = wm * 64 + mt * 16 + (lane & 15);
        aRowOff[mt] = (uint32_t)(r * 128); aX7[mt] = r & 7;
    }
    uint32_t bRowOff[2]; int bX7[2];
    #pragma unroll
    for (int p = 0; p < 2; p++) {
        int r = wn * 32 + p * 16 + (lane & 15);
        bRowOff[p] = (uint32_t)(r * 128); bX7[p] = r & 7;
    }
    const int lh = lane >> 4;

    float acc[4][4][4];
    #pragma unroll
    for (int i = 0; i < 4; i++)
        #pragma unroll
        for (int j = 0; j < 4; j++)
            #pragma unroll
            for (int k = 0; k < 4; k++) acc[i][j][k] = 0.0f;

    auto load_stage = [&](int ch, uint32_t st) {
        #pragma unroll
        for (int j = 0; j < 12; j++) cp16(st + so[j], gp[j] + ch * 8);
    };

    // prologue: 3 stages in flight
    load_stage(0, sbase);                            CP_COMMIT();
    if (NCH > 1) load_stage(1, sbase + STAGE_B);     CP_COMMIT();
    if (NCH > 2) load_stage(2, sbase + 2 * STAGE_B); CP_COMMIT();

    for (int i = 0; i < NCH; ++i) {
        CP_WAIT2();
        __syncthreads();
        const uint32_t st = sbase + (uint32_t)(i & 3) * STAGE_B;

        #pragma unroll
        for (int ks = 0; ks < 4; ks++) {           // four K16 steps per chunk
            const int qb = ks * 2 + lh;

            uint32_t ah[4][4], al[4][4];
            #pragma unroll
            for (int mt = 0; mt < 4; mt++) {
                uint32_t x = (uint32_t)((qb ^ aX7[mt]) << 4);
                LDSM4(ah[mt][0], ah[mt][1], ah[mt][2], ah[mt][3], st + aRowOff[mt] + x);
                LDSM4(al[mt][0], al[mt][1], al[mt][2], al[mt][3], st + 16384 + aRowOff[mt] + x);
            }
            uint32_t bh[4][2];
            #pragma unroll
            for (int p = 0; p < 2; p++) {
                uint32_t off = bRowOff[p] + (uint32_t)((qb ^ bX7[p]) << 4);
                uint32_t t0, t1, t2, t3;
                LDSM4(t0, t1, t2, t3, st + 32768 + off);
                bh[p*2][0] = t0; bh[p*2+1][0] = t1; bh[p*2][1] = t2; bh[p*2+1][1] = t3;
            }
            // product-major: 16 independent accumulators between reuse
            #pragma unroll
            for (int mt = 0; mt < 4; mt++)
                #pragma unroll
                for (int nt = 0; nt < 4; nt++)
                    MMA16816(acc[mt][nt], ah[mt], bh[nt]);
            #pragma unroll
            for (int mt = 0; mt < 4; mt++)
                #pragma unroll
                for (int nt = 0; nt < 4; nt++)
                    MMA16816(acc[mt][nt], al[mt], bh[nt]);
        }

        int nxt = i + 3;
        if (nxt < NCH) load_stage(nxt, sbase + (uint32_t)(nxt & 3) * STAGE_B);
        CP_COMMIT();
    }

    // -------- epilogue --------
    const int g  = lane >> 2;
    const int c2 = (lane & 3) * 2;
    #pragma unroll
    for (int nt = 0; nt < 4; nt++) {
        const int col = bn + wn * 32 + nt * 8 + c2;
        float2 bv = __ldg((const float2*)(bias + col));
        #pragma unroll
        for (int mt = 0; mt < 4; mt++) {
            const int row0 = bm + wm * 64 + mt * 16 + g;
            float v0 = acc[mt][nt][0] + bv.x;
            float v1 = acc[mt][nt][1] + bv.y;
            float v2 = acc[mt][nt][2] + bv.x;
            float v3 = acc[mt][nt][3] + bv.y;
            if (MISH) {
                v0 = mish_acc(v0); v1 = mish_acc(v1);
                v2 = mish_acc(v2); v3 = mish_acc(v3);
                __half h0 = __float2half(v0), h1 = __float2half(v1);
                __half h2 = __float2half(v2), h3 = __float2half(v3);
                __half2 hv0 = __halves2half2(h0, h1);
                __half2 hv1 = __halves2half2(h2, h3);
                __half2 lv0 = __halves2half2(
                    __float2half(v0 - __half2float(h0)),
                    __float2half(v1 - __half2float(h1)));
                __half2 lv1 = __halves2half2(
                    __float2half(v2 - __half2float(h2)),
                    __float2half(v3 - __half2float(h3)));
                *(__half2*)(OHi + (size_t)row0 * ldo + col)       = hv0;
                *(__half2*)(OHi + (size_t)(row0 + 8) * ldo + col) = hv1;
                *(__half2*)(OLo + (size_t)row0 * ldo + col)       = lv0;
                *(__half2*)(OLo + (size_t)(row0 + 8) * ldo + col) = lv1;
            } else {
                *(float2*)(OF + (size_t)row0 * ldo + col)       = make_float2(v0, v1);
                *(float2*)(OF + (size_t)(row0 + 8) * ldo + col) = make_float2(v2, v3);
            }
        }
    }
}

// ---------------- deterministic 2-phase segment pooling ----------------
__global__ void __launch_bounds__(1024)
pool_partial(const float* __restrict__ S, const int* __restrict__ seg,
             int n_tok, float* __restrict__ P)
{
    const int gseg = blockIdx.x;
    const int sub  = threadIdx.x >> 8;
    const int col  = threadIdx.x & 255;
    const int chunk = blockIdx.y * 4 + sub;

    int lo = 0, hi = n_tok;
    while (lo < hi) { int m = (lo + hi) >> 1; if (seg[m] < gseg) lo = m + 1; else hi = m; }
    const int s = lo;
    lo = s; hi = n_tok;
    while (lo < hi) { int m = (lo + hi) >> 1; if (seg[m] < gseg + 1) lo = m + 1; else hi = m; }
    const int e = lo;

    const int len = e - s;
    const int L = (len + PCHUNK - 1) / PCHUNK;
    const int cs = s + chunk * L;
    const int ce = min(cs + L, e);

    float a0 = 0.f, a1 = 0.f, a2 = 0.f, a3 = 0.f;
    int t = cs;
    for (; t + 4 <= ce; t += 4) {
        a0 += S[(size_t)(t + 0) * DOUT + col];
        a1 += S[(size_t)(t + 1) * DOUT + col];
        a2 += S[(size_t)(t + 2) * DOUT + col];
        a3 += S[(size_t)(t + 3) * DOUT + col];
    }
    float acc = (a0 + a1) + (a2 + a3);
    for (; t < ce; t++) acc += S[(size_t)t * DOUT + col];
    P[((size_t)gseg * PCHUNK + chunk) * DOUT + col] = acc;
}

__global__ void __launch_bounds__(256)
pool_final(const float* __restrict__ P, float* __restrict__ out)
{
    const int gseg = blockIdx.x, col = threadIdx.x;
    float acc = 0.f;
    #pragma unroll
    for (int c = 0; c < PCHUNK; c++)
        acc += P[((size_t)gseg * PCHUNK + c) * DOUT + col];
    out[(size_t)gseg * DOUT + col] = acc;
}

// ---------------- launch ----------------
extern "C" void kernel_launch(void* const* d_in, const int* in_sizes, int n_in,
                              void* d_out, int out_size)
{
    const float* hidden   = (const float*)d_in[0];
    const float* W1       = (const float*)d_in[1];
    const float* b1       = (const float*)d_in[2];
    const float* W2       = (const float*)d_in[3];
    const float* b2       = (const float*)d_in[4];
    const int*   flat_idx = (const int*)d_in[5];
    const int*   seg      = (const int*)d_in[6];
    float*       out      = (float*)d_out;

    const int n_tok = in_sizes[5];
    const int n_img = out_size / DOUT;
    const int mpad  = ((n_tok + 127) / 128) * 128;

    __half *xhi, *xlo, *w1h, *w2h, *hhi, *hlo;
    float *sbuf, *pbuf;
    cudaGetSymbolAddress((void**)&xhi, g_Xhi);
    cudaGetSymbolAddress((void**)&xlo, g_Xlo);
    cudaGetSymbolAddress((void**)&w1h, g_W1h);
    cudaGetSymbolAddress((void**)&w2h, g_W2h);
    cudaGetSymbolAddress((void**)&hhi, g_Hhi);
    cudaGetSymbolAddress((void**)&hlo, g_Hlo);
    cudaGetSymbolAddress((void**)&sbuf, g_S);
    cudaGetSymbolAddress((void**)&pbuf, g_P);

    cudaFuncSetAttribute(mma_gemm<HDIM, true>,
                         cudaFuncAttributeMaxDynamicSharedMemorySize, GEMM_SMEM);
    cudaFuncSetAttribute(mma_gemm<DMID, false>,
                         cudaFuncAttributeMaxDynamicSharedMemorySize, GEMM_SMEM);

    // 1) splits / conversions
    {
        long long t4 = (long long)mpad * HDIM / 4;
        split_fp16<<<(unsigned)((t4 + 255) / 256), 256>>>(hidden, flat_idx, n_tok, t4, HDIM, xhi, xlo);
        long long w1t = (long long)DMID * HDIM / 4;
        split_fp16<<<(unsigned)((w1t + 255) / 256), 256>>>(W1, nullptr, DMID, w1t, HDIM, w1h, nullptr);
        long long w2t = (long long)DOUT * DMID / 4;
        split_fp16<<<(unsigned)((w2t + 255) / 256), 256>>>(W2, nullptr, DOUT, w2t, DMID, w2h, nullptr);
    }
    // 2) GEMM1 + bias + mish -> H (fp16 hi/lo)
    {
        dim3 g(DMID / 128, mpad / 128);
        mma_gemm<HDIM, true><<<g, 256, GEMM_SMEM>>>(xhi, xlo, w1h, b1,
                                                    hhi, hlo, nullptr, DMID);
    }
    // 3) GEMM2 + bias -> S (fp32)
    {
        dim3 g(DOUT / 128, mpad / 128);
        mma_gemm<DMID, false><<<g, 256, GEMM_SMEM>>>(hhi, hlo, w2h, b2,
                                                     nullptr, nullptr, sbuf, DOUT);
    }
    // 4) pooling (2-phase deterministic)
    {
        dim3 gp(n_img, PCHUNK / 4);
        pool_partial<<<gp, 1024>>>(sbuf, seg, n_tok, pbuf);
        pool_final<<<n_img, 256>>>(pbuf, out);
    }
}

// round 6
// speedup vs baseline: 3.9065x; 1.0041x over previous
#include <cuda_runtime.h>
#include <cuda_fp16.h>
#include <cstdint>

// ---------------------------------------------------------------------------
// VLMSpatialHead via mma.sync (HMMA fp16) on sm_103:
//   X   = hidden[flat_idx]              [N_TOK, 2048]
//   Hm  = mish(X @ W1^T + b1)           [N_TOK, 1024]
//   S   = Hm @ W2^T + b2                [N_TOK, 256]
//   out = segment_sum(S, segment_ids)   [N_IMG, 256]
// R5: fp16 2-product scheme — activations split hi/lo fp16 (exact),
//     weights single fp16 (error 2^-12 stat) -> 2/3 the MMA work of the
//     bf16 3-product scheme. 4-stage cp.async ring, hoisted addressing.
// ---------------------------------------------------------------------------

#define NTOK_MAX 32768
#define HDIM     2048
#define DMID     1024
#define DOUT     256
#define PCHUNK   16

// ---------------- scratch (device globals; no allocs) ----------------
__device__ __align__(256) __half g_Xhi[(size_t)NTOK_MAX * HDIM];
__device__ __align__(256) __half g_Xlo[(size_t)NTOK_MAX * HDIM];
__device__ __align__(256) __half g_W1h[(size_t)DMID * HDIM];
__device__ __align__(256) __half g_W2h[(size_t)DOUT * DMID];
__device__ __align__(256) __half g_Hhi[(size_t)NTOK_MAX * DMID];
__device__ __align__(256) __half g_Hlo[(size_t)NTOK_MAX * DMID];
__device__ __align__(256) float  g_S  [(size_t)NTOK_MAX * DOUT];
__device__ __align__(256) float  g_P  [64 * PCHUNK * DOUT];

// ---------------- helpers ----------------
__device__ __forceinline__ uint32_t smem_u32(const void* p) {
    uint32_t a;
    asm("{ .reg .u64 t; cvta.to.shared.u64 t, %1; cvt.u32.u64 %0, t; }" : "=r"(a) : "l"(p));
    return a;
}
__device__ __forceinline__ void cp16(uint32_t saddr, const void* gaddr) {
    asm volatile("cp.async.cg.shared.global [%0], [%1], 16;" :: "r"(saddr), "l"(gaddr));
}
#define CP_COMMIT() asm volatile("cp.async.commit_group;" ::: "memory")
#define CP_WAIT2()  asm volatile("cp.async.wait_group 2;"  ::: "memory")

#define LDSM4(r0, r1, r2, r3, a) \
    asm volatile("ldmatrix.sync.aligned.m8n8.x4.shared.b16 {%0,%1,%2,%3}, [%4];" \
                 : "=r"(r0), "=r"(r1), "=r"(r2), "=r"(r3) : "r"(a))

#define MMA16816(c, a, b) \
    asm volatile("mma.sync.aligned.m16n8k16.row.col.f32.f16.f16.f32 " \
                 "{%0,%1,%2,%3}, {%4,%5,%6,%7}, {%8,%9}, {%0,%1,%2,%3};" \
                 : "+f"((c)[0]), "+f"((c)[1]), "+f"((c)[2]), "+f"((c)[3]) \
                 : "r"((a)[0]), "r"((a)[1]), "r"((a)[2]), "r"((a)[3]), \
                   "r"((b)[0]), "r"((b)[1]))

__device__ __forceinline__ float mish_acc(float x) {
    // mish(x) = x * u/(u+2), u = e^x (e^x + 2); precise expf for accuracy.
    float t = expf(fminf(x, 20.0f));
    float u = t * (t + 2.0f);
    return x * (u / (u + 2.0f));
}

// ---------------- fp32 -> fp16 hi/lo split (optional gather + pad) ----
// If lo == nullptr, only the hi (rounded) half is written (for weights).
__global__ void __launch_bounds__(256)
split_fp16(const float* __restrict__ src, const int* __restrict__ gidx,
           int rows_valid, long long total4, int K,
           __half* __restrict__ hi, __half* __restrict__ lo)
{
    long long i = (long long)blockIdx.x * 256 + threadIdx.x;
    if (i >= total4) return;
    int k4 = K >> 2;
    int row = (int)(i / k4);
    int c   = (int)(i % k4);
    float4 v = make_float4(0.f, 0.f, 0.f, 0.f);
    if (row < rows_valid) {
        size_t srow = gidx ? (size_t)gidx[row] : (size_t)row;
        v = *(const float4*)(src + srow * (size_t)K + (size_t)c * 4);
    }
    float vv[4] = {v.x, v.y, v.z, v.w};
    __half h[4];
    #pragma unroll
    for (int j = 0; j < 4; j++) h[j] = __float2half(vv[j]);
    __half2 h0 = __halves2half2(h[0], h[1]);
    __half2 h1 = __halves2half2(h[2], h[3]);
    uint2 hp;
    hp.x = *(uint32_t*)&h0; hp.y = *(uint32_t*)&h1;
    *(uint2*)(hi + i * 4) = hp;
    if (lo) {
        __half l[4];
        #pragma unroll
        for (int j = 0; j < 4; j++) l[j] = __float2half(vv[j] - __half2float(h[j]));
        __half2 l0 = __halves2half2(l[0], l[1]);
        __half2 l1 = __halves2half2(l[2], l[3]);
        uint2 lp;
        lp.x = *(uint32_t*)&l0; lp.y = *(uint32_t*)&l1;
        *(uint2*)(lo + i * 4) = lp;
    }
}

// ---------------- HMMA GEMM: 128x128 CTA tile, BK=64, 4-stage cp.async ----
// Stage layout (48KB): [Ahi 16K][Alo 16K][W 16K], each 128 rows x 128B,
// full SW128 swizzle (quad ^= row&7).
#define STAGE_B   49152
#define GEMM_SMEM (4 * STAGE_B)

template<int KD, bool MISH>
__global__ void __launch_bounds__(256, 1)
mma_gemm(const __half* __restrict__ Ahi, const __half* __restrict__ Alo,
         const __half* __restrict__ W,
         const float* __restrict__ bias,
         __half* __restrict__ OHi, __half* __restrict__ OLo,
         float* __restrict__ OF, int ldo)
{
    extern __shared__ __align__(128) char sm[];
    const uint32_t sbase = smem_u32(sm);
    const int tid  = threadIdx.x;
    const int lane = tid & 31;
    const int warp = tid >> 5;
    const int wm   = warp >> 2;   // 0..1 -> 64 rows
    const int wn   = warp & 3;    // 0..3 -> 32 cols
    const int bm   = blockIdx.y * 128;
    const int bn   = blockIdx.x * 128;

    constexpr int NCH = KD / 64;        // K chunks of 64 fp16 (128B)
    const int krow4   = KD / 8;         // row stride in uint4

    // ---- hoisted cp.async addressing: 12 chunks/thread/stage ----
    const uint4* gp[12];
    uint32_t     so[12];
    {
        const uint4* srcs[3] = { (const uint4*)Ahi, (const uint4*)Alo, (const uint4*)W };
        #pragma unroll
        for (int m = 0; m < 3; m++) {
            const int rb = (m < 2) ? bm : bn;
            #pragma unroll
            for (int it = 0; it < 4; it++) {
                int e = tid + it * 256, r = e >> 3, q = e & 7;
                int j = m * 4 + it;
                gp[j] = srcs[m] + (size_t)(rb + r) * krow4 + q;
                so[j] = (uint32_t)(m * 16384 + r * 128 + ((q ^ (r & 7)) << 4));
            }
        }
    }
    // ---- hoisted ldmatrix row bases ----
    uint32_t aRowOff[4]; int aX7[4];
    #pragma unroll
    for (int mt = 0; mt < 4; mt++) {
        int r = wm * 64 + mt * 16 + (lane & 15);
        aRowOff[mt] = (uint32_t)(r * 128); aX7[mt] = r & 7;
    }
    uint32_t bRowOff[2]; int bX7[2];
    #pragma unroll
    for (int p = 0; p < 2; p++) {
        int r = wn * 32 + p * 16 + (lane & 15);
        bRowOff[p] = (uint32_t)(r * 128); bX7[p] = r & 7;
    }
    const int lh = lane >> 4;

    float acc[4][4][4];
    #pragma unroll
    for (int i = 0; i < 4; i++)
        #pragma unroll
        for (int j = 0; j < 4; j++)
            #pragma unroll
            for (int k = 0; k < 4; k++) acc[i][j][k] = 0.0f;

    auto load_stage = [&](int ch, uint32_t st) {
        #pragma unroll
        for (int j = 0; j < 12; j++) cp16(st + so[j], gp[j] + ch * 8);
    };

    // prologue: 3 stages in flight
    load_stage(0, sbase);                            CP_COMMIT();
    if (NCH > 1) load_stage(1, sbase + STAGE_B);     CP_COMMIT();
    if (NCH > 2) load_stage(2, sbase + 2 * STAGE_B); CP_COMMIT();

    for (int i = 0; i < NCH; ++i) {
        CP_WAIT2();
        __syncthreads();
        const uint32_t st = sbase + (uint32_t)(i & 3) * STAGE_B;

        #pragma unroll
        for (int ks = 0; ks < 4; ks++) {           // four K16 steps per chunk
            const int qb = ks * 2 + lh;

            uint32_t ah[4][4], al[4][4];
            #pragma unroll
            for (int mt = 0; mt < 4; mt++) {
                uint32_t x = (uint32_t)((qb ^ aX7[mt]) << 4);
                LDSM4(ah[mt][0], ah[mt][1], ah[mt][2], ah[mt][3], st + aRowOff[mt] + x);
                LDSM4(al[mt][0], al[mt][1], al[mt][2], al[mt][3], st + 16384 + aRowOff[mt] + x);
            }
            uint32_t bh[4][2];
            #pragma unroll
            for (int p = 0; p < 2; p++) {
                uint32_t off = bRowOff[p] + (uint32_t)((qb ^ bX7[p]) << 4);
                uint32_t t0, t1, t2, t3;
                LDSM4(t0, t1, t2, t3, st + 32768 + off);
                bh[p*2][0] = t0; bh[p*2+1][0] = t1; bh[p*2][1] = t2; bh[p*2+1][1] = t3;
            }
            // product-major: 16 independent accumulators between reuse
            #pragma unroll
            for (int mt = 0; mt < 4; mt++)
                #pragma unroll
                for (int nt = 0; nt < 4; nt++)
                    MMA16816(acc[mt][nt], ah[mt], bh[nt]);
            #pragma unroll
            for (int mt = 0; mt < 4; mt++)
                #pragma unroll
                for (int nt = 0; nt < 4; nt++)
                    MMA16816(acc[mt][nt], al[mt], bh[nt]);
        }

        int nxt = i + 3;
        if (nxt < NCH) load_stage(nxt, sbase + (uint32_t)(nxt & 3) * STAGE_B);
        CP_COMMIT();
    }

    // -------- epilogue --------
    const int g  = lane >> 2;
    const int c2 = (lane & 3) * 2;
    #pragma unroll
    for (int nt = 0; nt < 4; nt++) {
        const int col = bn + wn * 32 + nt * 8 + c2;
        float2 bv = __ldg((const float2*)(bias + col));
        #pragma unroll
        for (int mt = 0; mt < 4; mt++) {
            const int row0 = bm + wm * 64 + mt * 16 + g;
            float v0 = acc[mt][nt][0] + bv.x;
            float v1 = acc[mt][nt][1] + bv.y;
            float v2 = acc[mt][nt][2] + bv.x;
            float v3 = acc[mt][nt][3] + bv.y;
            if (MISH) {
                v0 = mish_acc(v0); v1 = mish_acc(v1);
                v2 = mish_acc(v2); v3 = mish_acc(v3);
                __half h0 = __float2half(v0), h1 = __float2half(v1);
                __half h2 = __float2half(v2), h3 = __float2half(v3);
                __half2 hv0 = __halves2half2(h0, h1);
                __half2 hv1 = __halves2half2(h2, h3);
                __half2 lv0 = __halves2half2(
                    __float2half(v0 - __half2float(h0)),
                    __float2half(v1 - __half2float(h1)));
                __half2 lv1 = __halves2half2(
                    __float2half(v2 - __half2float(h2)),
                    __float2half(v3 - __half2float(h3)));
                *(__half2*)(OHi + (size_t)row0 * ldo + col)       = hv0;
                *(__half2*)(OHi + (size_t)(row0 + 8) * ldo + col) = hv1;
                *(__half2*)(OLo + (size_t)row0 * ldo + col)       = lv0;
                *(__half2*)(OLo + (size_t)(row0 + 8) * ldo + col) = lv1;
            } else {
                *(float2*)(OF + (size_t)row0 * ldo + col)       = make_float2(v0, v1);
                *(float2*)(OF + (size_t)(row0 + 8) * ldo + col) = make_float2(v2, v3);
            }
        }
    }
}

// ---------------- deterministic 2-phase segment pooling ----------------
__global__ void __launch_bounds__(1024)
pool_partial(const float* __restrict__ S, const int* __restrict__ seg,
             int n_tok, float* __restrict__ P)
{
    const int gseg = blockIdx.x;
    const int sub  = threadIdx.x >> 8;
    const int col  = threadIdx.x & 255;
    const int chunk = blockIdx.y * 4 + sub;

    int lo = 0, hi = n_tok;
    while (lo < hi) { int m = (lo + hi) >> 1; if (seg[m] < gseg) lo = m + 1; else hi = m; }
    const int s = lo;
    lo = s; hi = n_tok;
    while (lo < hi) { int m = (lo + hi) >> 1; if (seg[m] < gseg + 1) lo = m + 1; else hi = m; }
    const int e = lo;

    const int len = e - s;
    const int L = (len + PCHUNK - 1) / PCHUNK;
    const int cs = s + chunk * L;
    const int ce = min(cs + L, e);

    float a0 = 0.f, a1 = 0.f, a2 = 0.f, a3 = 0.f;
    int t = cs;
    for (; t + 4 <= ce; t += 4) {
        a0 += S[(size_t)(t + 0) * DOUT + col];
        a1 += S[(size_t)(t + 1) * DOUT + col];
        a2 += S[(size_t)(t + 2) * DOUT + col];
        a3 += S[(size_t)(t + 3) * DOUT + col];
    }
    float acc = (a0 + a1) + (a2 + a3);
    for (; t < ce; t++) acc += S[(size_t)t * DOUT + col];
    P[((size_t)gseg * PCHUNK + chunk) * DOUT + col] = acc;
}

__global__ void __launch_bounds__(256)
pool_final(const float* __restrict__ P, float* __restrict__ out)
{
    const int gseg = blockIdx.x, col = threadIdx.x;
    float acc = 0.f;
    #pragma unroll
    for (int c = 0; c < PCHUNK; c++)
        acc += P[((size_t)gseg * PCHUNK + c) * DOUT + col];
    out[(size_t)gseg * DOUT + col] = acc;
}

// ---------------- launch ----------------
extern "C" void kernel_launch(void* const* d_in, const int* in_sizes, int n_in,
                              void* d_out, int out_size)
{
    const float* hidden   = (const float*)d_in[0];
    const float* W1       = (const float*)d_in[1];
    const float* b1       = (const float*)d_in[2];
    const float* W2       = (const float*)d_in[3];
    const float* b2       = (const float*)d_in[4];
    const int*   flat_idx = (const int*)d_in[5];
    const int*   seg      = (const int*)d_in[6];
    float*       out      = (float*)d_out;

    const int n_tok = in_sizes[5];
    const int n_img = out_size / DOUT;
    const int mpad  = ((n_tok + 127) / 128) * 128;

    __half *xhi, *xlo, *w1h, *w2h, *hhi, *hlo;
    float *sbuf, *pbuf;
    cudaGetSymbolAddress((void**)&xhi, g_Xhi);
    cudaGetSymbolAddress((void**)&xlo, g_Xlo);
    cudaGetSymbolAddress((void**)&w1h, g_W1h);
    cudaGetSymbolAddress((void**)&w2h, g_W2h);
    cudaGetSymbolAddress((void**)&hhi, g_Hhi);
    cudaGetSymbolAddress((void**)&hlo, g_Hlo);
    cudaGetSymbolAddress((void**)&sbuf, g_S);
    cudaGetSymbolAddress((void**)&pbuf, g_P);

    cudaFuncSetAttribute(mma_gemm<HDIM, true>,
                         cudaFuncAttributeMaxDynamicSharedMemorySize, GEMM_SMEM);
    cudaFuncSetAttribute(mma_gemm<DMID, false>,
                         cudaFuncAttributeMaxDynamicSharedMemorySize, GEMM_SMEM);

    // 1) splits / conversions
    {
        long long t4 = (long long)mpad * HDIM / 4;
        split_fp16<<<(unsigned)((t4 + 255) / 256), 256>>>(hidden, flat_idx, n_tok, t4, HDIM, xhi, xlo);
        long long w1t = (long long)DMID * HDIM / 4;
        split_fp16<<<(unsigned)((w1t + 255) / 256), 256>>>(W1, nullptr, DMID, w1t, HDIM, w1h, nullptr);
        long long w2t = (long long)DOUT * DMID / 4;
        split_fp16<<<(unsigned)((w2t + 255) / 256), 256>>>(W2, nullptr, DOUT, w2t, DMID, w2h, nullptr);
    }
    // 2) GEMM1 + bias + mish -> H (fp16 hi/lo)
    {
        dim3 g(DMID / 128, mpad / 128);
        mma_gemm<HDIM, true><<<g, 256, GEMM_SMEM>>>(xhi, xlo, w1h, b1,
                                                    hhi, hlo, nullptr, DMID);
    }
    // 3) GEMM2 + bias -> S (fp32)
    {
        dim3 g(DOUT / 128, mpad / 128);
        mma_gemm<DMID, false><<<g, 256, GEMM_SMEM>>>(hhi, hlo, w2h, b2,
                                                     nullptr, nullptr, sbuf, DOUT);
    }
    // 4) pooling (2-phase deterministic)
    {
        dim3 gp(n_img, PCHUNK / 4);
        pool_partial<<<gp, 1024>>>(sbuf, seg, n_tok, pbuf);
        pool_final<<<n_img, 256>>>(pbuf, out);
    }
}